// round 3
// baseline (speedup 1.0000x reference)
#include <cuda_runtime.h>

// ============================================================================
// QuantumNAT: 4-qubit circuit, B=524288.
// out_q(x) = sum_{t in {1,cos,sin}^4} D_q[t] * prod_i basis_i[t_i]
// D (81 x float4 {D0,D1,D2,D3}) precomputed from weights by prep_kernel into
// g_coefStage, then copied into __constant__ c_coef (off the L1 port).
// Main kernel: 2 samples/thread, outputs packed in f32x2 pairs.
// ============================================================================

__constant__ float4 c_coef[81];
__device__ float4 g_coefStage[81];

// ---------------- complex helpers (prep only) ----------------
__device__ __forceinline__ float2 cmul(float2 a, float2 b) {
    return make_float2(a.x * b.x - a.y * b.y, a.x * b.y + a.y * b.x);
}
__device__ __forceinline__ float2 cmulcj(float2 a, float2 b) {  // conj(a)*b
    return make_float2(a.x * b.x + a.y * b.y, a.x * b.y - a.y * b.x);
}
__device__ __forceinline__ float2 cadd(float2 a, float2 b) {
    return make_float2(a.x + b.x, a.y + b.y);
}
__device__ __forceinline__ float2 csub(float2 a, float2 b) {
    return make_float2(a.x - b.x, a.y - b.y);
}

// 2x2 contraction against basis matrices:
//  t=0 (const): 1/2 (x00 + x11)
//  t=1 (cos):   1/2 (x00 - x11)
//  t=2 (sin):   1/2 * i * (x10 - x01)
__device__ __forceinline__ float2 ctr(float2 x00, float2 x01, float2 x10, float2 x11, int tsel) {
    if (tsel == 0) return make_float2(0.5f * (x00.x + x11.x), 0.5f * (x00.y + x11.y));
    if (tsel == 1) return make_float2(0.5f * (x00.x - x11.x), 0.5f * (x00.y - x11.y));
    return make_float2(0.5f * (x01.y - x10.y), 0.5f * (x10.x - x01.x));
}

// ============================================================================
// Prep kernel: one block, 256 threads (unchanged math from R1, new output
// layout: g_coefStage[tt] = float4{D0,D1,D2,D3}).
// ============================================================================
__global__ void prep_kernel(const float* __restrict__ w)
{
    __shared__ float2 Ug[12][2][2];
    __shared__ float2 Wm[16][16];             // Wm[m][col]
    __shared__ float2 Mq[4][16][16];
    __shared__ float2 T3[4][3][8][8];
    __shared__ float2 T2s[4][3][3][4][4];
    __shared__ float2 T1s[4][3][3][3][2][2];

    const int t = threadIdx.x;

    // --- 1. fused gate matrices -------------------------------------------
    if (t < 12) {
        float ax = 0.5f * w[t * 3 + 0];
        float ay = 0.5f * w[t * 3 + 1];
        float az = 0.5f * w[t * 3 + 2];
        float sx = sinf(ax), cx = cosf(ax);
        float sy = sinf(ay), cy = cosf(ay);
        float sz = sinf(az), cz = cosf(az);
        float2 a00 = make_float2( cy * cx,  sy * sx);
        float2 a01 = make_float2(-sy * cx, -cy * sx);
        float2 a10 = make_float2( sy * cx, -cy * sx);
        float2 a11 = make_float2( cy * cx, -sy * sx);
        float2 e0 = make_float2(cz, -sz);
        float2 e1 = make_float2(cz,  sz);
        Ug[t][0][0] = cmul(e0, a00); Ug[t][0][1] = cmul(e0, a01);
        Ug[t][1][0] = cmul(e1, a10); Ug[t][1][1] = cmul(e1, a11);
    }
    __syncthreads();

    // --- 2. W columns in registers ----------------------------------------
    if (t < 16) {
        float2 col[16];
        #pragma unroll
        for (int m = 0; m < 16; m++) col[m] = make_float2((m == t) ? 1.0f : 0.0f, 0.0f);

        #pragma unroll
        for (int l = 0; l < 3; l++) {
            #pragma unroll
            for (int i = 0; i < 4; i++) {
                float2 u00 = Ug[l * 4 + i][0][0], u01 = Ug[l * 4 + i][0][1];
                float2 u10 = Ug[l * 4 + i][1][0], u11 = Ug[l * 4 + i][1][1];
                const int str = 1 << (3 - i);
                #pragma unroll
                for (int p = 0; p < 8; p++) {
                    const int low = p & (str - 1);
                    const int m0  = ((p - low) << 1) | low;
                    const int m1  = m0 | str;
                    float2 a = col[m0], b = col[m1];
                    col[m0] = cadd(cmul(u00, a), cmul(u01, b));
                    col[m1] = cadd(cmul(u10, a), cmul(u11, b));
                }
            }
            #pragma unroll
            for (int i = 0; i < 3; i++) {
                const int cmask = 1 << (3 - i);
                const int tmask = 1 << (2 - i);
                #pragma unroll
                for (int m = 0; m < 16; m++) {
                    if ((m & cmask) && !(m & tmask)) {
                        float2 tmp = col[m];
                        col[m] = col[m | tmask];
                        col[m | tmask] = tmp;
                    }
                }
            }
        }
        #pragma unroll
        for (int m = 0; m < 16; m++) Wm[m][t] = col[m];
    }
    __syncthreads();

    // --- 3. M_q = W^dag Z_q W ---------------------------------------------
    {
        const int j = t >> 4, k = t & 15;
        float2 a0 = make_float2(0.f, 0.f), a1 = a0, a2 = a0, a3 = a0;
        #pragma unroll
        for (int m = 0; m < 16; m++) {
            float2 p = cmulcj(Wm[m][j], Wm[m][k]);
            a0 = (m & 8) ? csub(a0, p) : cadd(a0, p);
            a1 = (m & 4) ? csub(a1, p) : cadd(a1, p);
            a2 = (m & 2) ? csub(a2, p) : cadd(a2, p);
            a3 = (m & 1) ? csub(a3, p) : cadd(a3, p);
        }
        Mq[0][j][k] = a0; Mq[1][j][k] = a1; Mq[2][j][k] = a2; Mq[3][j][k] = a3;
    }
    __syncthreads();

    // --- 4a. contract qubit 3 (LSB) ---------------------------------------
    for (int e = t; e < 768; e += 256) {
        const int q = e / 192, r = e % 192, t3 = r / 64, ab = r % 64;
        const int a = ab >> 3, b = ab & 7;
        T3[q][t3][a][b] = ctr(Mq[q][2 * a][2 * b],     Mq[q][2 * a][2 * b + 1],
                              Mq[q][2 * a + 1][2 * b], Mq[q][2 * a + 1][2 * b + 1], t3);
    }
    __syncthreads();

    // --- 4b. contract qubit 2 ---------------------------------------------
    for (int e = t; e < 576; e += 256) {
        const int q = e / 144, r = e % 144, t2 = r / 48, r2 = r % 48;
        const int t3 = r2 / 16, ab = r2 % 16, a = ab >> 2, b = ab & 3;
        T2s[q][t2][t3][a][b] = ctr(T3[q][t3][2 * a][2 * b],     T3[q][t3][2 * a][2 * b + 1],
                                   T3[q][t3][2 * a + 1][2 * b], T3[q][t3][2 * a + 1][2 * b + 1], t2);
    }
    __syncthreads();

    // --- 4c. contract qubit 1 ---------------------------------------------
    for (int e = t; e < 432; e += 256) {
        const int q = e / 108, r = e % 108, t1 = r / 36, r2 = r % 36;
        const int t2 = r2 / 12, r3 = r2 % 12, t3 = r3 / 4, ab = r3 & 3;
        const int a = ab >> 1, b = ab & 1;
        T1s[q][t1][t2][t3][a][b] = ctr(T2s[q][t2][t3][2 * a][2 * b],     T2s[q][t2][t3][2 * a][2 * b + 1],
                                       T2s[q][t2][t3][2 * a + 1][2 * b], T2s[q][t2][t3][2 * a + 1][2 * b + 1], t1);
    }
    __syncthreads();

    // --- 4d. contract qubit 0, keep real part, write float4{D0..D3} -------
    for (int e = t; e < 324; e += 256) {
        const int q = e / 81, tt = e % 81;
        const int t0 = tt / 27, r = tt % 27, t1 = r / 9, r2 = r % 9, t2 = r2 / 3, t3 = r2 % 3;
        float2 x00 = T1s[q][t1][t2][t3][0][0];
        float2 x01 = T1s[q][t1][t2][t3][0][1];
        float2 x10 = T1s[q][t1][t2][t3][1][0];
        float2 x11 = T1s[q][t1][t2][t3][1][1];
        float d;
        if (t0 == 0)      d = 0.5f * (x00.x + x11.x);
        else if (t0 == 1) d = 0.5f * (x00.x - x11.x);
        else              d = 0.5f * (x01.y - x10.y);
        reinterpret_cast<float*>(g_coefStage)[tt * 4 + q] = d;
    }
}

// ============================================================================
// Main kernel: 2 samples per thread, outputs packed in f32x2 pairs.
// ============================================================================
__device__ __forceinline__ unsigned long long pk(float a, float b) {
    unsigned long long r;
    asm("mov.b64 %0, {%1, %2};" : "=l"(r) : "f"(a), "f"(b));
    return r;
}
__device__ __forceinline__ void upk(float& a, float& b, unsigned long long v) {
    asm("mov.b64 {%0, %1}, %2;" : "=f"(a), "=f"(b) : "l"(v));
}
__device__ __forceinline__ unsigned long long m2(unsigned long long a, unsigned long long b) {
    unsigned long long r;
    asm("mul.rn.f32x2 %0, %1, %2;" : "=l"(r) : "l"(a), "l"(b));
    return r;
}
__device__ __forceinline__ unsigned long long f2(unsigned long long a, unsigned long long b,
                                                 unsigned long long c) {
    unsigned long long r;
    asm("fma.rn.f32x2 %0, %1, %2, %3;" : "=l"(r) : "l"(a), "l"(b), "l"(c));
    return r;
}

__global__ __launch_bounds__(256)
void qnat_main(const float4* __restrict__ x, float4* __restrict__ out, int nPairs)
{
    const int gid = blockIdx.x * 256 + threadIdx.x;
    if (gid >= nPairs) return;

    const float4 xa = x[2 * gid];
    const float4 xb = x[2 * gid + 1];

    float sA0, cA0, sA1, cA1, sA2, cA2, sA3, cA3;
    float sB0, cB0, sB1, cB1, sB2, cB2, sB3, cB3;
    __sincosf(xa.x, &sA0, &cA0);  __sincosf(xb.x, &sB0, &cB0);
    __sincosf(xa.y, &sA1, &cA1);  __sincosf(xb.y, &sB1, &cB1);
    __sincosf(xa.z, &sA2, &cA2);  __sincosf(xb.z, &sB2, &cB2);
    __sincosf(xa.w, &sA3, &cA3);  __sincosf(xb.w, &sB3, &cB3);

    // duplicated packed sincos values (products of dup values stay dup)
    const unsigned long long cA0d = pk(cA0, cA0), sA0d = pk(sA0, sA0);
    const unsigned long long cA1d = pk(cA1, cA1), sA1d = pk(sA1, sA1);
    const unsigned long long cA2d = pk(cA2, cA2), sA2d = pk(sA2, sA2);
    const unsigned long long cA3d = pk(cA3, cA3), sA3d = pk(sA3, sA3);
    const unsigned long long cB0d = pk(cB0, cB0), sB0d = pk(sB0, sB0);
    const unsigned long long cB1d = pk(cB1, cB1), sB1d = pk(sB1, sB1);
    const unsigned long long cB2d = pk(cB2, cB2), sB2d = pk(sB2, sB2);
    const unsigned long long cB3d = pk(cB3, cB3), sB3d = pk(sB3, sB3);

    // b23 basis (qubits 2,3), duplicated, per sample. Index k = t2*3 + t3.
    unsigned long long bA[9], bB[9];
    bA[1] = cA3d; bA[2] = sA3d; bA[3] = cA2d;
    bA[4] = m2(cA2d, cA3d); bA[5] = m2(cA2d, sA3d);
    bA[6] = sA2d; bA[7] = m2(sA2d, cA3d); bA[8] = m2(sA2d, sA3d);
    bB[1] = cB3d; bB[2] = sB3d; bB[3] = cB2d;
    bB[4] = m2(cB2d, cB3d); bB[5] = m2(cB2d, sB3d);
    bB[6] = sB2d; bB[7] = m2(sB2d, cB3d); bB[8] = m2(sB2d, sB3d);

    const ulonglong2* cc = reinterpret_cast<const ulonglong2*>(c_coef);

    unsigned long long aA01 = 0, aA23 = 0, aB01 = 0, aB23 = 0;

    #pragma unroll
    for (int j = 0; j < 9; j++) {
        // k = 0: b23 = 1 -> direct init
        ulonglong2 cv0 = cc[j * 9];
        unsigned long long iA01 = cv0.x, iA23 = cv0.y;
        unsigned long long iB01 = cv0.x, iB23 = cv0.y;
        #pragma unroll
        for (int k = 1; k < 9; k++) {
            const ulonglong2 cv = cc[j * 9 + k];
            iA01 = f2(cv.x, bA[k], iA01);
            iA23 = f2(cv.y, bA[k], iA23);
            iB01 = f2(cv.x, bB[k], iB01);
            iB23 = f2(cv.y, bB[k], iB23);
        }
        if (j == 0) {
            // b01 = 1
            aA01 = iA01; aA23 = iA23; aB01 = iB01; aB23 = iB23;
        } else {
            unsigned long long bjA, bjB;
            switch (j) {
                case 1: bjA = cA1d;            bjB = cB1d;            break;
                case 2: bjA = sA1d;            bjB = sB1d;            break;
                case 3: bjA = cA0d;            bjB = cB0d;            break;
                case 4: bjA = m2(cA0d, cA1d);  bjB = m2(cB0d, cB1d);  break;
                case 5: bjA = m2(cA0d, sA1d);  bjB = m2(cB0d, sB1d);  break;
                case 6: bjA = sA0d;            bjB = sB0d;            break;
                case 7: bjA = m2(sA0d, cA1d);  bjB = m2(sB0d, cB1d);  break;
                default: bjA = m2(sA0d, sA1d); bjB = m2(sB0d, sB1d);  break;
            }
            aA01 = f2(bjA, iA01, aA01);
            aA23 = f2(bjA, iA23, aA23);
            aB01 = f2(bjB, iB01, aB01);
            aB23 = f2(bjB, iB23, aB23);
        }
    }

    float4 oa, ob;
    upk(oa.x, oa.y, aA01); upk(oa.z, oa.w, aA23);
    upk(ob.x, ob.y, aB01); upk(ob.z, ob.w, aB23);
    out[2 * gid]     = oa;
    out[2 * gid + 1] = ob;
}

// ============================================================================
extern "C" void kernel_launch(void* const* d_in, const int* in_sizes, int n_in,
                              void* d_out, int out_size)
{
    const float* x = (const float*)d_in[0];        // [B,4] float32
    const float* w = (const float*)d_in[1];        // [3,4,3] float32

    prep_kernel<<<1, 256>>>(w);

    // Copy computed coefficients into __constant__ memory (graph-capturable
    // device-to-device async copy; no allocation).
    void* dst = nullptr;
    void* src = nullptr;
    cudaGetSymbolAddress(&dst, c_coef);
    cudaGetSymbolAddress(&src, g_coefStage);
    cudaMemcpyAsync(dst, src, 81 * sizeof(float4), cudaMemcpyDeviceToDevice);

    const int B = in_sizes[0] / 4;                 // 524288
    const int nPairs = B / 2;                      // 262144
    const int grid = (nPairs + 255) / 256;         // 1024
    qnat_main<<<grid, 256>>>((const float4*)x, (float4*)d_out, nPairs);
}

// round 4
// speedup vs baseline: 1.5656x; 1.5656x over previous
#include <cuda_runtime.h>

// ============================================================================
// QuantumNAT: 4-qubit circuit, B=524288.
// out_q(x) = sum_{t in {1,cos,sin}^4} D_q[t] * prod_i basis_i[t_i]
// D (81 x float4 {D0,D1,D2,D3}) precomputed by prep_kernel into g_coefStage.
// Main kernel: 2 samples/thread, coefficients staged in SMEM (one 16B
// broadcast LDS per (j,k) feeding 4 packed f32x2 FMAs), PDL overlap with prep.
// ============================================================================

__device__ float4 g_coefStage[81];

// ---------------- complex helpers (prep only) ----------------
__device__ __forceinline__ float2 cmul(float2 a, float2 b) {
    return make_float2(a.x * b.x - a.y * b.y, a.x * b.y + a.y * b.x);
}
__device__ __forceinline__ float2 cmulcj(float2 a, float2 b) {  // conj(a)*b
    return make_float2(a.x * b.x + a.y * b.y, a.x * b.y - a.y * b.x);
}
__device__ __forceinline__ float2 cadd(float2 a, float2 b) {
    return make_float2(a.x + b.x, a.y + b.y);
}
__device__ __forceinline__ float2 csub(float2 a, float2 b) {
    return make_float2(a.x - b.x, a.y - b.y);
}

// 2x2 contraction against basis matrices:
//  t=0 (const): 1/2 (x00 + x11)
//  t=1 (cos):   1/2 (x00 - x11)
//  t=2 (sin):   1/2 * i * (x10 - x01)
__device__ __forceinline__ float2 ctr(float2 x00, float2 x01, float2 x10, float2 x11, int tsel) {
    if (tsel == 0) return make_float2(0.5f * (x00.x + x11.x), 0.5f * (x00.y + x11.y));
    if (tsel == 1) return make_float2(0.5f * (x00.x - x11.x), 0.5f * (x00.y - x11.y));
    return make_float2(0.5f * (x01.y - x10.y), 0.5f * (x10.x - x01.x));
}

// ============================================================================
// Prep kernel: one block, 256 threads. Output: g_coefStage[tt] = {D0,D1,D2,D3}.
// ============================================================================
__global__ void prep_kernel(const float* __restrict__ w)
{
    __shared__ float2 Ug[12][2][2];
    __shared__ float2 Wm[16][16];             // Wm[m][col]
    __shared__ float2 Mq[4][16][16];
    __shared__ float2 T3[4][3][8][8];
    __shared__ float2 T2s[4][3][3][4][4];
    __shared__ float2 T1s[4][3][3][3][2][2];

    const int t = threadIdx.x;

    // --- 1. fused gate matrices -------------------------------------------
    if (t < 12) {
        float ax = 0.5f * w[t * 3 + 0];
        float ay = 0.5f * w[t * 3 + 1];
        float az = 0.5f * w[t * 3 + 2];
        float sx = sinf(ax), cx = cosf(ax);
        float sy = sinf(ay), cy = cosf(ay);
        float sz = sinf(az), cz = cosf(az);
        float2 a00 = make_float2( cy * cx,  sy * sx);
        float2 a01 = make_float2(-sy * cx, -cy * sx);
        float2 a10 = make_float2( sy * cx, -cy * sx);
        float2 a11 = make_float2( cy * cx, -sy * sx);
        float2 e0 = make_float2(cz, -sz);
        float2 e1 = make_float2(cz,  sz);
        Ug[t][0][0] = cmul(e0, a00); Ug[t][0][1] = cmul(e0, a01);
        Ug[t][1][0] = cmul(e1, a10); Ug[t][1][1] = cmul(e1, a11);
    }
    __syncthreads();

    // --- 2. W columns in registers ----------------------------------------
    if (t < 16) {
        float2 col[16];
        #pragma unroll
        for (int m = 0; m < 16; m++) col[m] = make_float2((m == t) ? 1.0f : 0.0f, 0.0f);

        #pragma unroll
        for (int l = 0; l < 3; l++) {
            #pragma unroll
            for (int i = 0; i < 4; i++) {
                float2 u00 = Ug[l * 4 + i][0][0], u01 = Ug[l * 4 + i][0][1];
                float2 u10 = Ug[l * 4 + i][1][0], u11 = Ug[l * 4 + i][1][1];
                const int str = 1 << (3 - i);
                #pragma unroll
                for (int p = 0; p < 8; p++) {
                    const int low = p & (str - 1);
                    const int m0  = ((p - low) << 1) | low;
                    const int m1  = m0 | str;
                    float2 a = col[m0], b = col[m1];
                    col[m0] = cadd(cmul(u00, a), cmul(u01, b));
                    col[m1] = cadd(cmul(u10, a), cmul(u11, b));
                }
            }
            #pragma unroll
            for (int i = 0; i < 3; i++) {
                const int cmask = 1 << (3 - i);
                const int tmask = 1 << (2 - i);
                #pragma unroll
                for (int m = 0; m < 16; m++) {
                    if ((m & cmask) && !(m & tmask)) {
                        float2 tmp = col[m];
                        col[m] = col[m | tmask];
                        col[m | tmask] = tmp;
                    }
                }
            }
        }
        #pragma unroll
        for (int m = 0; m < 16; m++) Wm[m][t] = col[m];
    }
    __syncthreads();

    // --- 3. M_q = W^dag Z_q W ---------------------------------------------
    {
        const int j = t >> 4, k = t & 15;
        float2 a0 = make_float2(0.f, 0.f), a1 = a0, a2 = a0, a3 = a0;
        #pragma unroll
        for (int m = 0; m < 16; m++) {
            float2 p = cmulcj(Wm[m][j], Wm[m][k]);
            a0 = (m & 8) ? csub(a0, p) : cadd(a0, p);
            a1 = (m & 4) ? csub(a1, p) : cadd(a1, p);
            a2 = (m & 2) ? csub(a2, p) : cadd(a2, p);
            a3 = (m & 1) ? csub(a3, p) : cadd(a3, p);
        }
        Mq[0][j][k] = a0; Mq[1][j][k] = a1; Mq[2][j][k] = a2; Mq[3][j][k] = a3;
    }
    __syncthreads();

    // --- 4a. contract qubit 3 (LSB) ---------------------------------------
    for (int e = t; e < 768; e += 256) {
        const int q = e / 192, r = e % 192, t3 = r / 64, ab = r % 64;
        const int a = ab >> 3, b = ab & 7;
        T3[q][t3][a][b] = ctr(Mq[q][2 * a][2 * b],     Mq[q][2 * a][2 * b + 1],
                              Mq[q][2 * a + 1][2 * b], Mq[q][2 * a + 1][2 * b + 1], t3);
    }
    __syncthreads();

    // --- 4b. contract qubit 2 ---------------------------------------------
    for (int e = t; e < 576; e += 256) {
        const int q = e / 144, r = e % 144, t2 = r / 48, r2 = r % 48;
        const int t3 = r2 / 16, ab = r2 % 16, a = ab >> 2, b = ab & 3;
        T2s[q][t2][t3][a][b] = ctr(T3[q][t3][2 * a][2 * b],     T3[q][t3][2 * a][2 * b + 1],
                                   T3[q][t3][2 * a + 1][2 * b], T3[q][t3][2 * a + 1][2 * b + 1], t2);
    }
    __syncthreads();

    // --- 4c. contract qubit 1 ---------------------------------------------
    for (int e = t; e < 432; e += 256) {
        const int q = e / 108, r = e % 108, t1 = r / 36, r2 = r % 36;
        const int t2 = r2 / 12, r3 = r2 % 12, t3 = r3 / 4, ab = r3 & 3;
        const int a = ab >> 1, b = ab & 1;
        T1s[q][t1][t2][t3][a][b] = ctr(T2s[q][t2][t3][2 * a][2 * b],     T2s[q][t2][t3][2 * a][2 * b + 1],
                                       T2s[q][t2][t3][2 * a + 1][2 * b], T2s[q][t2][t3][2 * a + 1][2 * b + 1], t1);
    }
    __syncthreads();

    // --- 4d. contract qubit 0, keep real part, write float4{D0..D3} -------
    for (int e = t; e < 324; e += 256) {
        const int q = e / 81, tt = e % 81;
        const int t0 = tt / 27, r = tt % 27, t1 = r / 9, r2 = r % 9, t2 = r2 / 3, t3 = r2 % 3;
        float2 x00 = T1s[q][t1][t2][t3][0][0];
        float2 x01 = T1s[q][t1][t2][t3][0][1];
        float2 x10 = T1s[q][t1][t2][t3][1][0];
        float2 x11 = T1s[q][t1][t2][t3][1][1];
        float d;
        if (t0 == 0)      d = 0.5f * (x00.x + x11.x);
        else if (t0 == 1) d = 0.5f * (x00.x - x11.x);
        else              d = 0.5f * (x01.y - x10.y);
        reinterpret_cast<float*>(g_coefStage)[tt * 4 + q] = d;
    }
    // Allow the PDL-dependent main kernel to begin its prologue.
    cudaTriggerProgrammaticLaunchCompletion();
}

// ============================================================================
// Main kernel: 2 samples per thread, outputs packed in f32x2 pairs.
// ============================================================================
__device__ __forceinline__ unsigned long long pk(float a, float b) {
    unsigned long long r;
    asm("mov.b64 %0, {%1, %2};" : "=l"(r) : "f"(a), "f"(b));
    return r;
}
__device__ __forceinline__ void upk(float& a, float& b, unsigned long long v) {
    asm("mov.b64 {%0, %1}, %2;" : "=f"(a), "=f"(b) : "l"(v));
}
__device__ __forceinline__ unsigned long long m2(unsigned long long a, unsigned long long b) {
    unsigned long long r;
    asm("mul.rn.f32x2 %0, %1, %2;" : "=l"(r) : "l"(a), "l"(b));
    return r;
}
__device__ __forceinline__ unsigned long long f2(unsigned long long a, unsigned long long b,
                                                 unsigned long long c) {
    unsigned long long r;
    asm("fma.rn.f32x2 %0, %1, %2, %3;" : "=l"(r) : "l"(a), "l"(b), "l"(c));
    return r;
}

__global__ __launch_bounds__(256)
void qnat_main(const float4* __restrict__ x, float4* __restrict__ out, int nPairs)
{
    __shared__ ulonglong2 sc[81];   // {D0,D1},{D2,D3} per t-index

    const int gid = blockIdx.x * 256 + threadIdx.x;
    const bool active = (gid < nPairs);

    // ---- coefficient-independent prologue (overlaps prep via PDL) --------
    float4 xa = make_float4(0.f, 0.f, 0.f, 0.f), xb = xa;
    if (active) { xa = x[2 * gid]; xb = x[2 * gid + 1]; }

    float sA0, cA0, sA1, cA1, sA2, cA2, sA3, cA3;
    float sB0, cB0, sB1, cB1, sB2, cB2, sB3, cB3;
    __sincosf(xa.x, &sA0, &cA0);  __sincosf(xb.x, &sB0, &cB0);
    __sincosf(xa.y, &sA1, &cA1);  __sincosf(xb.y, &sB1, &cB1);
    __sincosf(xa.z, &sA2, &cA2);  __sincosf(xb.z, &sB2, &cB2);
    __sincosf(xa.w, &sA3, &cA3);  __sincosf(xb.w, &sB3, &cB3);

    const unsigned long long cA0d = pk(cA0, cA0), sA0d = pk(sA0, sA0);
    const unsigned long long cA1d = pk(cA1, cA1), sA1d = pk(sA1, sA1);
    const unsigned long long cA2d = pk(cA2, cA2), sA2d = pk(sA2, sA2);
    const unsigned long long cA3d = pk(cA3, cA3), sA3d = pk(sA3, sA3);
    const unsigned long long cB0d = pk(cB0, cB0), sB0d = pk(sB0, sB0);
    const unsigned long long cB1d = pk(cB1, cB1), sB1d = pk(sB1, sB1);
    const unsigned long long cB2d = pk(cB2, cB2), sB2d = pk(sB2, sB2);
    const unsigned long long cB3d = pk(cB3, cB3), sB3d = pk(sB3, sB3);

    // b23 basis (qubits 2,3), duplicated, per sample. Index k = t2*3 + t3.
    unsigned long long bA[9], bB[9];
    bA[1] = cA3d; bA[2] = sA3d; bA[3] = cA2d;
    bA[4] = m2(cA2d, cA3d); bA[5] = m2(cA2d, sA3d);
    bA[6] = sA2d; bA[7] = m2(sA2d, cA3d); bA[8] = m2(sA2d, sA3d);
    bB[1] = cB3d; bB[2] = sB3d; bB[3] = cB2d;
    bB[4] = m2(cB2d, cB3d); bB[5] = m2(cB2d, sB3d);
    bB[6] = sB2d; bB[7] = m2(sB2d, cB3d); bB[8] = m2(sB2d, sB3d);

    // ---- wait for prep's coefficients, stage them into SMEM --------------
    cudaGridDependencySynchronize();
    if (threadIdx.x < 81)
        sc[threadIdx.x] = reinterpret_cast<const ulonglong2*>(g_coefStage)[threadIdx.x];
    __syncthreads();
    if (!active) return;

    unsigned long long aA01 = 0, aA23 = 0, aB01 = 0, aB23 = 0;

    #pragma unroll
    for (int j = 0; j < 9; j++) {
        // k = 0: b23 = 1 -> direct init
        ulonglong2 cv0 = sc[j * 9];
        unsigned long long iA01 = cv0.x, iA23 = cv0.y;
        unsigned long long iB01 = cv0.x, iB23 = cv0.y;
        #pragma unroll
        for (int k = 1; k < 9; k++) {
            const ulonglong2 cv = sc[j * 9 + k];
            iA01 = f2(cv.x, bA[k], iA01);
            iA23 = f2(cv.y, bA[k], iA23);
            iB01 = f2(cv.x, bB[k], iB01);
            iB23 = f2(cv.y, bB[k], iB23);
        }
        if (j == 0) {
            aA01 = iA01; aA23 = iA23; aB01 = iB01; aB23 = iB23;
        } else {
            unsigned long long bjA, bjB;
            switch (j) {
                case 1: bjA = cA1d;            bjB = cB1d;            break;
                case 2: bjA = sA1d;            bjB = sB1d;            break;
                case 3: bjA = cA0d;            bjB = cB0d;            break;
                case 4: bjA = m2(cA0d, cA1d);  bjB = m2(cB0d, cB1d);  break;
                case 5: bjA = m2(cA0d, sA1d);  bjB = m2(cB0d, sB1d);  break;
                case 6: bjA = sA0d;            bjB = sB0d;            break;
                case 7: bjA = m2(sA0d, cA1d);  bjB = m2(sB0d, cB1d);  break;
                default: bjA = m2(sA0d, sA1d); bjB = m2(sB0d, sB1d);  break;
            }
            aA01 = f2(bjA, iA01, aA01);
            aA23 = f2(bjA, iA23, aA23);
            aB01 = f2(bjB, iB01, aB01);
            aB23 = f2(bjB, iB23, aB23);
        }
    }

    float4 oa, ob;
    upk(oa.x, oa.y, aA01); upk(oa.z, oa.w, aA23);
    upk(ob.x, ob.y, aB01); upk(ob.z, ob.w, aB23);
    out[2 * gid]     = oa;
    out[2 * gid + 1] = ob;
}

// ============================================================================
extern "C" void kernel_launch(void* const* d_in, const int* in_sizes, int n_in,
                              void* d_out, int out_size)
{
    const float* x = (const float*)d_in[0];        // [B,4] float32
    const float* w = (const float*)d_in[1];        // [3,4,3] float32

    prep_kernel<<<1, 256>>>(w);

    const int B = in_sizes[0] / 4;                 // 524288
    const int nPairs = B / 2;                      // 262144
    const int grid = (nPairs + 255) / 256;         // 1024

    cudaLaunchConfig_t cfg = {};
    cfg.gridDim  = dim3((unsigned)grid);
    cfg.blockDim = dim3(256);
    cfg.dynamicSmemBytes = 0;
    cudaLaunchAttribute attr[1];
    attr[0].id = cudaLaunchAttributeProgrammaticStreamSerialization;
    attr[0].val.programmaticStreamSerializationAllowed = 1;
    cfg.attrs = attr;
    cfg.numAttrs = 1;
    cudaLaunchKernelEx(&cfg, qnat_main, (const float4*)x, (float4*)d_out, nPairs);
}